// round 2
// baseline (speedup 1.0000x reference)
#include <cuda_runtime.h>
#include <math.h>

#define N_NODES 20000
#define N_EDGES 160000
#define EMB_DIM 16
#define N_BASIS 16
#define MUL_IN 8
#define MUL_OUT 4
// W layout per edge: [3][8][8][4] = 768
#define OUT_PER_NODE 36

// ---------------- scratch (static device globals; no allocation) ----------------
__device__ float d_Ai[N_NODES * 8];          // node features
__device__ float d_g3T[64 * N_EDGES];        // transposed: [c][e]  (41 MB)
__device__ float d_M[512 * 96];              // permuted fc_w4: [(c*8+u)][(l*32+v*4+w)]
__device__ float d_cnt[N_NODES];

// ---------------- kernel 0: zero output + cnt ----------------
__global__ void k_zero(float* out, int out_size) {
    int i = blockIdx.x * blockDim.x + threadIdx.x;
    if (i < out_size) out[i] = 0.0f;
    if (i < N_NODES) d_cnt[i] = 0.0f;
}

// ---------------- kernel 1: edge counts ----------------
__global__ void k_count(const int* __restrict__ edge_dst) {
    int e = blockIdx.x * blockDim.x + threadIdx.x;
    if (e < N_EDGES) atomicAdd(&d_cnt[edge_dst[e]], 1.0f);
}

// ---------------- kernel 2: node MLP -> Ai ----------------
__global__ __launch_bounds__(256) void k_node(
    const float* __restrict__ emb_table,
    const float* __restrict__ w1, const float* __restrict__ b1,
    const float* __restrict__ w2, const float* __restrict__ b2,
    const float* __restrict__ w3, const float* __restrict__ b3,
    const int* __restrict__ A)
{
    __shared__ float s_w1[16 * 64];
    __shared__ float s_w2[64 * 32];
    __shared__ float s_w3[32 * 8];
    __shared__ float s_b1[64];
    __shared__ float s_b2[32];
    __shared__ float s_b3[8];
    int tid = threadIdx.x;
    for (int i = tid; i < 16 * 64; i += blockDim.x) s_w1[i] = w1[i];
    for (int i = tid; i < 64 * 32; i += blockDim.x) s_w2[i] = w2[i];
    for (int i = tid; i < 32 * 8;  i += blockDim.x) s_w3[i] = w3[i];
    if (tid < 64) s_b1[tid] = b1[tid];
    if (tid < 32) s_b2[tid] = b2[tid];
    if (tid < 8)  s_b3[tid] = b3[tid];
    __syncthreads();

    int n = blockIdx.x * blockDim.x + tid;
    if (n >= N_NODES) return;

    int a = A[n];
    float e[16];
    #pragma unroll
    for (int i = 0; i < 16; i++) e[i] = emb_table[a * 16 + i];

    float h1[64];
    #pragma unroll
    for (int j = 0; j < 64; j++) h1[j] = s_b1[j];
    #pragma unroll
    for (int i = 0; i < 16; i++) {
        float ei = e[i];
        #pragma unroll
        for (int j = 0; j < 64; j++) h1[j] += ei * s_w1[i * 64 + j];
    }
    #pragma unroll
    for (int j = 0; j < 64; j++) {
        float x = h1[j];
        h1[j] = x / (1.0f + __expf(-x));
    }

    float h2[32];
    #pragma unroll
    for (int j = 0; j < 32; j++) h2[j] = s_b2[j];
    #pragma unroll
    for (int i = 0; i < 64; i++) {
        float hi = h1[i];
        #pragma unroll
        for (int j = 0; j < 32; j++) h2[j] += hi * s_w2[i * 32 + j];
    }
    #pragma unroll
    for (int j = 0; j < 32; j++) {
        float x = h2[j];
        h2[j] = x / (1.0f + __expf(-x));
    }

    float ai[8];
    #pragma unroll
    for (int j = 0; j < 8; j++) ai[j] = s_b3[j];
    #pragma unroll
    for (int i = 0; i < 32; i++) {
        float hi = h2[i];
        #pragma unroll
        for (int j = 0; j < 8; j++) ai[j] += hi * s_w3[i * 8 + j];
    }
    #pragma unroll
    for (int j = 0; j < 8; j++) d_Ai[n * 8 + j] = ai[j];
}

// ---------------- kernel 3: permute fc_w4 -> M ----------------
// fc_w4: [c(64)][l(3)][u(8)][v(8)][w(4)] -> M[(c*8+u)][l*32 + v*4 + w]
__global__ void k_permute(const float* __restrict__ fc_w4) {
    int idx = blockIdx.x * blockDim.x + threadIdx.x;
    if (idx >= 64 * 768) return;
    int c = idx / 768;
    int rem = idx - c * 768;
    int l = rem / 256;
    int rem2 = rem - l * 256;
    int u = rem2 / 32;
    int vw = rem2 - u * 32;   // v*4+w
    d_M[(c * 8 + u) * 96 + l * 32 + vw] = fc_w4[idx];
}

// ---------------- geometry helper ----------------
__device__ __forceinline__ void edge_geom(
    const float* __restrict__ pos, const int* __restrict__ batch,
    const float* __restrict__ shifts, const float* __restrict__ cell,
    int e, int s, int d, float& ex, float& ey, float& ez, float& r)
{
    float sx = shifts[e * 3 + 0], sy = shifts[e * 3 + 1], sz = shifts[e * 3 + 2];
    int b = batch[s];
    const float* C = cell + b * 9;
    float shx = sx * C[0] + sy * C[3] + sz * C[6];
    float shy = sx * C[1] + sy * C[4] + sz * C[7];
    float shz = sx * C[2] + sy * C[5] + sz * C[8];
    ex = pos[d * 3 + 0] - pos[s * 3 + 0] + shx;
    ey = pos[d * 3 + 1] - pos[s * 3 + 1] + shy;
    ez = pos[d * 3 + 2] - pos[s * 3 + 2] + shz;
    r = sqrtf(ex * ex + ey * ey + ez * ez);
}

// ---------------- kernel 4: edge radial chain -> g3 (transposed store) ----------------
__global__ __launch_bounds__(256) void k_radial(
    const float* __restrict__ pos, const int* __restrict__ batch,
    const int* __restrict__ src, const int* __restrict__ dst,
    const float* __restrict__ shifts, const float* __restrict__ cell,
    const float* __restrict__ fw1, const float* __restrict__ fw2,
    const float* __restrict__ fw3)
{
    __shared__ float s_w1[16 * 64];
    __shared__ float s_w2[64 * 64];
    __shared__ float s_w3[64 * 64];
    int tid = threadIdx.x;
    for (int i = tid; i < 16 * 64; i += blockDim.x) s_w1[i] = fw1[i];
    for (int i = tid; i < 64 * 64; i += blockDim.x) s_w2[i] = fw2[i];
    for (int i = tid; i < 64 * 64; i += blockDim.x) s_w3[i] = fw3[i];
    __syncthreads();

    int e = blockIdx.x * blockDim.x + tid;
    if (e >= N_EDGES) return;

    int s = src[e], d = dst[e];
    float ex, ey, ez, r;
    edge_geom(pos, batch, shifts, cell, e, s, d, ex, ey, ez, r);

    // radial basis: centers = 5*(i+1)/17, step = 5/17
    const float step = 5.0f / 17.0f;
    const float inv_step = 17.0f / 5.0f;
    const float rb_scale = 4.0f / 1.12f;

    float g1[64];
    #pragma unroll
    for (int j = 0; j < 64; j++) g1[j] = 0.0f;
    #pragma unroll
    for (int i = 0; i < 16; i++) {
        float c = step * (float)(i + 1);
        float t = (r - c) * inv_step;
        float rb = __expf(-t * t) * rb_scale;
        #pragma unroll
        for (int j = 0; j < 64; j++) g1[j] += rb * s_w1[i * 64 + j];
    }
    #pragma unroll
    for (int j = 0; j < 64; j++) {
        float x = g1[j] * 0.25f;           // / sqrt(16)
        g1[j] = x / (1.0f + __expf(-x));
    }

    float g2[64];
    #pragma unroll
    for (int j = 0; j < 64; j++) g2[j] = 0.0f;
    #pragma unroll
    for (int i = 0; i < 64; i++) {
        float gi = g1[i];
        #pragma unroll
        for (int j = 0; j < 64; j++) g2[j] += gi * s_w2[i * 64 + j];
    }
    #pragma unroll
    for (int j = 0; j < 64; j++) {
        float x = g2[j] * 0.125f;
        g2[j] = x / (1.0f + __expf(-x));
    }

    float g3[64];
    #pragma unroll
    for (int j = 0; j < 64; j++) g3[j] = 0.0f;
    #pragma unroll
    for (int i = 0; i < 64; i++) {
        float gi = g2[i];
        #pragma unroll
        for (int j = 0; j < 64; j++) g3[j] += gi * s_w3[i * 64 + j];
    }
    #pragma unroll
    for (int j = 0; j < 64; j++) {
        float x = g3[j] * 0.125f;
        float v = x / (1.0f + __expf(-x));
        d_g3T[j * N_EDGES + e] = v;        // transposed: coalesced read in k_main
    }
}

// ---------------- kernel 5: main contraction + SH epilogue + scatter ----------------
__global__ __launch_bounds__(256) void k_main(
    const float* __restrict__ pos, const int* __restrict__ batch,
    const int* __restrict__ src, const int* __restrict__ dst,
    const float* __restrict__ shifts, const float* __restrict__ cell,
    float* __restrict__ out)
{
    extern __shared__ float sM[];  // 512*96 floats = 192 KB
    for (int i = threadIdx.x; i < 512 * 96; i += blockDim.x) sM[i] = d_M[i];
    __syncthreads();

    for (int e = blockIdx.x * blockDim.x + threadIdx.x; e < N_EDGES;
         e += gridDim.x * blockDim.x) {
        int s = src[e], d = dst[e];
        float ex, ey, ez, r;
        edge_geom(pos, batch, shifts, cell, e, s, d, ex, ey, ez, r);
        float inv_r = 1.0f / fmaxf(r, 1e-9f);
        float x = ex * inv_r, y = ey * inv_r, z = ez * inv_r;

        // Ai gathers (vectorized)
        const float4* Ai4 = (const float4*)d_Ai;
        float4 a0 = Ai4[s * 2], a1 = Ai4[s * 2 + 1];
        float As[8] = {a0.x, a0.y, a0.z, a0.w, a1.x, a1.y, a1.z, a1.w};
        float4 b0 = Ai4[d * 2], b1 = Ai4[d * 2 + 1];
        float Ad[8] = {b0.x, b0.y, b0.z, b0.w, b1.x, b1.y, b1.z, b1.w};

        float S[96];
        #pragma unroll
        for (int j = 0; j < 96; j++) S[j] = 0.0f;

        #pragma unroll 1
        for (int c = 0; c < 64; c++) {
            float gc = __ldg(&d_g3T[c * N_EDGES + e]);
            const float4* row = (const float4*)&sM[c * 8 * 96];
            #pragma unroll
            for (int u = 0; u < 8; u++) {
                float f = gc * As[u];
                #pragma unroll
                for (int j = 0; j < 24; j++) {
                    float4 m = row[u * 24 + j];
                    S[j * 4 + 0] += f * m.x;
                    S[j * 4 + 1] += f * m.y;
                    S[j * 4 + 2] += f * m.z;
                    S[j * 4 + 3] += f * m.w;
                }
            }
        }

        // contract v with Ai_dst; total scale = (1/8 from w) * (1/8 from MUL_IN)
        const float scale = 1.0f / 64.0f;
        float Sl[3][4];
        #pragma unroll
        for (int l = 0; l < 3; l++) {
            #pragma unroll
            for (int w = 0; w < 4; w++) {
                float acc = 0.0f;
                #pragma unroll
                for (int v = 0; v < 8; v++) acc += Ad[v] * S[l * 32 + v * 4 + w];
                Sl[l][w] = acc * scale;
            }
        }

        // spherical harmonics
        const float s3 = 1.7320508075688772f;   // sqrt(3)
        const float s15 = 3.872983346207417f;   // sqrt(15)
        const float s5 = 2.23606797749979f;     // sqrt(5)
        float sh1[3] = {s3 * y, s3 * z, s3 * x};
        float sh2[5] = {s15 * x * y, s15 * y * z, 0.5f * s5 * (3.0f * z * z - 1.0f),
                        s15 * x * z, 0.5f * s15 * (x * x - y * y)};

        float* od = out + d * OUT_PER_NODE;
        #pragma unroll
        for (int w = 0; w < 4; w++) atomicAdd(&od[w], Sl[0][w]);
        #pragma unroll
        for (int w = 0; w < 4; w++)
            #pragma unroll
            for (int k = 0; k < 3; k++)
                atomicAdd(&od[4 + w * 3 + k], Sl[1][w] * sh1[k]);
        #pragma unroll
        for (int w = 0; w < 4; w++)
            #pragma unroll
            for (int k = 0; k < 5; k++)
                atomicAdd(&od[16 + w * 5 + k], Sl[2][w] * sh2[k]);
    }
}

// ---------------- kernel 6: divide by clipped count ----------------
__global__ void k_div(float* __restrict__ out, int out_size) {
    int i = blockIdx.x * blockDim.x + threadIdx.x;
    if (i >= out_size) return;
    int n = i / OUT_PER_NODE;
    out[i] = out[i] / fmaxf(d_cnt[n], 1.0f);
}

// ---------------- launch ----------------
extern "C" void kernel_launch(void* const* d_in, const int* in_sizes, int n_in,
                              void* d_out, int out_size) {
    const float* pos      = (const float*)d_in[0];
    const int*   A        = (const int*)d_in[1];
    const int*   batch    = (const int*)d_in[2];
    const int*   edge_src = (const int*)d_in[3];
    const int*   edge_dst = (const int*)d_in[4];
    const float* shifts   = (const float*)d_in[5];
    const float* cell     = (const float*)d_in[6];
    const float* emb      = (const float*)d_in[7];
    const float* fit_w1   = (const float*)d_in[8];
    const float* fit_b1   = (const float*)d_in[9];
    const float* fit_w2   = (const float*)d_in[10];
    const float* fit_b2   = (const float*)d_in[11];
    const float* fit_w3   = (const float*)d_in[12];
    const float* fit_b3   = (const float*)d_in[13];
    const float* fc_w1    = (const float*)d_in[14];
    const float* fc_w2    = (const float*)d_in[15];
    const float* fc_w3    = (const float*)d_in[16];
    const float* fc_w4    = (const float*)d_in[17];
    float* out = (float*)d_out;

    // opt-in to 192 KB dynamic smem for the main kernel (idempotent)
    cudaFuncSetAttribute(k_main, cudaFuncAttributeMaxDynamicSharedMemorySize,
                         512 * 96 * (int)sizeof(float));

    int zn = out_size > N_NODES ? out_size : N_NODES;
    k_zero<<<(zn + 255) / 256, 256>>>(out, out_size);
    k_count<<<(N_EDGES + 255) / 256, 256>>>(edge_dst);
    k_node<<<(N_NODES + 255) / 256, 256>>>(emb, fit_w1, fit_b1, fit_w2, fit_b2,
                                           fit_w3, fit_b3, A);
    k_permute<<<(64 * 768 + 255) / 256, 256>>>(fc_w4);
    k_radial<<<(N_EDGES + 255) / 256, 256>>>(pos, batch, edge_src, edge_dst,
                                             shifts, cell, fc_w1, fc_w2, fc_w3);
    k_main<<<148, 256, 512 * 96 * sizeof(float)>>>(pos, batch, edge_src, edge_dst,
                                                   shifts, cell, out);
    k_div<<<(out_size + 255) / 256, 256>>>(out, out_size);
}

// round 3
// speedup vs baseline: 1.9387x; 1.9387x over previous
#include <cuda_runtime.h>
#include <math.h>

#define N_NODES 20000
#define N_EDGES 160000
#define OUT_PER_NODE 36

typedef unsigned long long u64;

// ---------------- packed f32x2 helpers (sm_103a FFMA2 path) ----------------
__device__ __forceinline__ u64 pack2(float a, float b) {
    u64 r; asm("mov.b64 %0, {%1,%2};" : "=l"(r) : "f"(a), "f"(b)); return r;
}
__device__ __forceinline__ void unpack2(u64 v, float& a, float& b) {
    asm("mov.b64 {%0,%1}, %2;" : "=f"(a), "=f"(b) : "l"(v));
}
__device__ __forceinline__ void ffma2(u64& d, u64 a, u64 b) {
    asm("fma.rn.f32x2 %0, %1, %2, %0;" : "+l"(d) : "l"(a), "l"(b));
}

// ---------------- scratch ----------------
__device__ float d_Ai[N_NODES * 8];
__device__ float d_g3T[64 * N_EDGES];           // [c][e], coalesced in k_main
__device__ float d_M[3 * 512 * 32];             // [l][(c*8+u)][(v*4+w)]
__device__ float d_cnt[N_NODES];

// ---------------- kernel 0: zero output + cnt ----------------
__global__ void k_zero(float* out, int out_size) {
    int i = blockIdx.x * blockDim.x + threadIdx.x;
    if (i < out_size) out[i] = 0.0f;
    if (i < N_NODES) d_cnt[i] = 0.0f;
}

// ---------------- kernel 1: edge counts ----------------
__global__ void k_count(const int* __restrict__ edge_dst) {
    int e = blockIdx.x * blockDim.x + threadIdx.x;
    if (e < N_EDGES) atomicAdd(&d_cnt[edge_dst[e]], 1.0f);
}

// ---------------- kernel 2: node MLP -> Ai ----------------
__global__ __launch_bounds__(256) void k_node(
    const float* __restrict__ emb_table,
    const float* __restrict__ w1, const float* __restrict__ b1,
    const float* __restrict__ w2, const float* __restrict__ b2,
    const float* __restrict__ w3, const float* __restrict__ b3,
    const int* __restrict__ A)
{
    __shared__ __align__(16) float s_w1[16 * 64];
    __shared__ __align__(16) float s_w2[64 * 32];
    __shared__ __align__(16) float s_w3[32 * 8];
    __shared__ float s_b1[64];
    __shared__ float s_b2[32];
    __shared__ float s_b3[8];
    int tid = threadIdx.x;
    for (int i = tid; i < 16 * 64; i += blockDim.x) s_w1[i] = w1[i];
    for (int i = tid; i < 64 * 32; i += blockDim.x) s_w2[i] = w2[i];
    for (int i = tid; i < 32 * 8;  i += blockDim.x) s_w3[i] = w3[i];
    if (tid < 64) s_b1[tid] = b1[tid];
    if (tid < 32) s_b2[tid] = b2[tid];
    if (tid < 8)  s_b3[tid] = b3[tid];
    __syncthreads();

    int n = blockIdx.x * blockDim.x + tid;
    if (n >= N_NODES) return;

    int a = A[n];
    float e[16];
    #pragma unroll
    for (int i = 0; i < 16; i++) e[i] = emb_table[a * 16 + i];

    float h1[64];
    #pragma unroll
    for (int j = 0; j < 64; j++) h1[j] = s_b1[j];
    #pragma unroll
    for (int i = 0; i < 16; i++) {
        float ei = e[i];
        #pragma unroll
        for (int j = 0; j < 64; j++) h1[j] += ei * s_w1[i * 64 + j];
    }
    #pragma unroll
    for (int j = 0; j < 64; j++) { float x = h1[j]; h1[j] = x / (1.0f + __expf(-x)); }

    float h2[32];
    #pragma unroll
    for (int j = 0; j < 32; j++) h2[j] = s_b2[j];
    #pragma unroll
    for (int i = 0; i < 64; i++) {
        float hi = h1[i];
        #pragma unroll
        for (int j = 0; j < 32; j++) h2[j] += hi * s_w2[i * 32 + j];
    }
    #pragma unroll
    for (int j = 0; j < 32; j++) { float x = h2[j]; h2[j] = x / (1.0f + __expf(-x)); }

    float ai[8];
    #pragma unroll
    for (int j = 0; j < 8; j++) ai[j] = s_b3[j];
    #pragma unroll
    for (int i = 0; i < 32; i++) {
        float hi = h2[i];
        #pragma unroll
        for (int j = 0; j < 8; j++) ai[j] += hi * s_w3[i * 8 + j];
    }
    #pragma unroll
    for (int j = 0; j < 8; j++) d_Ai[n * 8 + j] = ai[j];
}

// ---------------- kernel 3: permute fc_w4 -> M[l][cu][vw] ----------------
// fc_w4 idx: c*768 + l*256 + u*32 + v*4 + w
__global__ void k_permute(const float* __restrict__ fc_w4) {
    int idx = blockIdx.x * blockDim.x + threadIdx.x;
    if (idx >= 64 * 768) return;
    int c = idx / 768;
    int rem = idx - c * 768;
    int l = rem / 256;
    int rem2 = rem - l * 256;
    int u = rem2 / 32;
    int vw = rem2 - u * 32;
    d_M[l * (512 * 32) + (c * 8 + u) * 32 + vw] = fc_w4[idx];
}

// ---------------- geometry helper ----------------
__device__ __forceinline__ void edge_geom(
    const float* __restrict__ pos, const int* __restrict__ batch,
    const float* __restrict__ shifts, const float* __restrict__ cell,
    int e, int s, int d, float& ex, float& ey, float& ez, float& r)
{
    float sx = shifts[e * 3 + 0], sy = shifts[e * 3 + 1], sz = shifts[e * 3 + 2];
    int b = batch[s];
    const float* C = cell + b * 9;
    float shx = sx * C[0] + sy * C[3] + sz * C[6];
    float shy = sx * C[1] + sy * C[4] + sz * C[7];
    float shz = sx * C[2] + sy * C[5] + sz * C[8];
    ex = pos[d * 3 + 0] - pos[s * 3 + 0] + shx;
    ey = pos[d * 3 + 1] - pos[s * 3 + 1] + shy;
    ez = pos[d * 3 + 2] - pos[s * 3 + 2] + shz;
    r = sqrtf(ex * ex + ey * ey + ez * ez);
}

// ---------------- kernel 4: edge radial chain -> g3 (packed FFMA2) ----------------
__global__ __launch_bounds__(256) void k_radial(
    const float* __restrict__ pos, const int* __restrict__ batch,
    const int* __restrict__ src, const int* __restrict__ dst,
    const float* __restrict__ shifts, const float* __restrict__ cell,
    const float* __restrict__ fw1, const float* __restrict__ fw2,
    const float* __restrict__ fw3)
{
    __shared__ __align__(16) float s_w1[16 * 64];
    __shared__ __align__(16) float s_w2[64 * 64];
    __shared__ __align__(16) float s_w3[64 * 64];
    int tid = threadIdx.x;
    for (int i = tid; i < 16 * 64; i += blockDim.x) s_w1[i] = fw1[i];
    for (int i = tid; i < 64 * 64; i += blockDim.x) s_w2[i] = fw2[i];
    for (int i = tid; i < 64 * 64; i += blockDim.x) s_w3[i] = fw3[i];
    __syncthreads();

    int e = blockIdx.x * blockDim.x + tid;
    if (e >= N_EDGES) return;

    int s = src[e], d = dst[e];
    float ex, ey, ez, r;
    edge_geom(pos, batch, shifts, cell, e, s, d, ex, ey, ez, r);

    const float step = 5.0f / 17.0f;
    const float inv_step = 17.0f / 5.0f;
    const float rb_scale = 4.0f / 1.12f;

    // layer 1: [16] -> [64]
    u64 acc[32];
    #pragma unroll
    for (int p = 0; p < 32; p++) acc[p] = 0ULL;
    #pragma unroll
    for (int i = 0; i < 16; i++) {
        float c = step * (float)(i + 1);
        float t = (r - c) * inv_step;
        float rb = __expf(-t * t) * rb_scale;
        u64 rr = pack2(rb, rb);
        const ulonglong2* row = (const ulonglong2*)&s_w1[i * 64];
        #pragma unroll
        for (int k = 0; k < 16; k++) {
            ulonglong2 m = row[k];
            ffma2(acc[2 * k + 0], rr, m.x);
            ffma2(acc[2 * k + 1], rr, m.y);
        }
    }
    float g[64];
    #pragma unroll
    for (int p = 0; p < 32; p++) {
        float a, b; unpack2(acc[p], a, b);
        a *= 0.25f; b *= 0.25f;
        g[2 * p + 0] = a / (1.0f + __expf(-a));
        g[2 * p + 1] = b / (1.0f + __expf(-b));
    }

    // layer 2: [64] -> [64]
    #pragma unroll
    for (int p = 0; p < 32; p++) acc[p] = 0ULL;
    #pragma unroll
    for (int i = 0; i < 64; i++) {
        u64 gi = pack2(g[i], g[i]);
        const ulonglong2* row = (const ulonglong2*)&s_w2[i * 64];
        #pragma unroll
        for (int k = 0; k < 16; k++) {
            ulonglong2 m = row[k];
            ffma2(acc[2 * k + 0], gi, m.x);
            ffma2(acc[2 * k + 1], gi, m.y);
        }
    }
    #pragma unroll
    for (int p = 0; p < 32; p++) {
        float a, b; unpack2(acc[p], a, b);
        a *= 0.125f; b *= 0.125f;
        g[2 * p + 0] = a / (1.0f + __expf(-a));
        g[2 * p + 1] = b / (1.0f + __expf(-b));
    }

    // layer 3: [64] -> [64]
    #pragma unroll
    for (int p = 0; p < 32; p++) acc[p] = 0ULL;
    #pragma unroll
    for (int i = 0; i < 64; i++) {
        u64 gi = pack2(g[i], g[i]);
        const ulonglong2* row = (const ulonglong2*)&s_w3[i * 64];
        #pragma unroll
        for (int k = 0; k < 16; k++) {
            ulonglong2 m = row[k];
            ffma2(acc[2 * k + 0], gi, m.x);
            ffma2(acc[2 * k + 1], gi, m.y);
        }
    }
    #pragma unroll
    for (int p = 0; p < 32; p++) {
        float a, b; unpack2(acc[p], a, b);
        a *= 0.125f; b *= 0.125f;
        d_g3T[(2 * p + 0) * N_EDGES + e] = a / (1.0f + __expf(-a));
        d_g3T[(2 * p + 1) * N_EDGES + e] = b / (1.0f + __expf(-b));
    }
}

// ---------------- kernel 5: main contraction (per-l blocks, packed FFMA2) ----------------
__global__ __launch_bounds__(256, 2) void k_main(
    const float* __restrict__ pos, const int* __restrict__ batch,
    const int* __restrict__ src, const int* __restrict__ dst,
    const float* __restrict__ shifts, const float* __restrict__ cell,
    float* __restrict__ out)
{
    extern __shared__ float sM[];  // 512*32 floats = 64 KB (this block's l slice)
    const int l = blockIdx.y;
    const float* Ml = d_M + l * (512 * 32);
    for (int i = threadIdx.x; i < 512 * 32; i += 256) sM[i] = Ml[i];
    __syncthreads();

    for (int e = blockIdx.x * 256 + threadIdx.x; e < N_EDGES;
         e += gridDim.x * 256) {
        int s = src[e], d = dst[e];

        const float4* Ai4 = (const float4*)d_Ai;
        float4 a0 = Ai4[s * 2], a1 = Ai4[s * 2 + 1];
        float As[8] = {a0.x, a0.y, a0.z, a0.w, a1.x, a1.y, a1.z, a1.w};
        float4 b0 = Ai4[d * 2], b1 = Ai4[d * 2 + 1];
        float Ad[8] = {b0.x, b0.y, b0.z, b0.w, b1.x, b1.y, b1.z, b1.w};

        u64 S2[16];
        #pragma unroll
        for (int p = 0; p < 16; p++) S2[p] = 0ULL;

        #pragma unroll 1
        for (int c = 0; c < 64; c++) {
            float gc = __ldg(&d_g3T[c * N_EDGES + e]);
            const float* base = &sM[c * 256];
            #pragma unroll
            for (int u = 0; u < 8; u++) {
                float f = gc * As[u];
                u64 ff = pack2(f, f);
                const ulonglong2* row = (const ulonglong2*)(base + u * 32);
                #pragma unroll
                for (int k = 0; k < 8; k++) {
                    ulonglong2 m = row[k];
                    ffma2(S2[2 * k + 0], ff, m.x);   // (v=k, w0,w1)
                    ffma2(S2[2 * k + 1], ff, m.y);   // (v=k, w2,w3)
                }
            }
        }

        // contract over v with Ai_dst
        u64 acc01 = 0ULL, acc23 = 0ULL;
        #pragma unroll
        for (int v = 0; v < 8; v++) {
            u64 av = pack2(Ad[v], Ad[v]);
            ffma2(acc01, av, S2[2 * v + 0]);
            ffma2(acc23, av, S2[2 * v + 1]);
        }
        float W[4];
        unpack2(acc01, W[0], W[1]);
        unpack2(acc23, W[2], W[3]);
        const float scale = 1.0f / 64.0f;  // (1/8 from w-norm) * (1/8 from MUL_IN)
        #pragma unroll
        for (int w = 0; w < 4; w++) W[w] *= scale;

        float* od = out + d * OUT_PER_NODE;
        if (l == 0) {
            #pragma unroll
            for (int w = 0; w < 4; w++) atomicAdd(&od[w], W[w]);
        } else {
            float ex, ey, ez, r;
            edge_geom(pos, batch, shifts, cell, e, s, d, ex, ey, ez, r);
            float inv_r = 1.0f / fmaxf(r, 1e-9f);
            float x = ex * inv_r, y = ey * inv_r, z = ez * inv_r;
            if (l == 1) {
                const float s3 = 1.7320508075688772f;
                float sh1[3] = {s3 * y, s3 * z, s3 * x};
                #pragma unroll
                for (int w = 0; w < 4; w++)
                    #pragma unroll
                    for (int k = 0; k < 3; k++)
                        atomicAdd(&od[4 + w * 3 + k], W[w] * sh1[k]);
            } else {
                const float s15 = 3.872983346207417f;
                const float s5 = 2.23606797749979f;
                float sh2[5] = {s15 * x * y, s15 * y * z,
                                0.5f * s5 * (3.0f * z * z - 1.0f),
                                s15 * x * z, 0.5f * s15 * (x * x - y * y)};
                #pragma unroll
                for (int w = 0; w < 4; w++)
                    #pragma unroll
                    for (int k = 0; k < 5; k++)
                        atomicAdd(&od[16 + w * 5 + k], W[w] * sh2[k]);
            }
        }
    }
}

// ---------------- kernel 6: divide by clipped count ----------------
__global__ void k_div(float* __restrict__ out, int out_size) {
    int i = blockIdx.x * blockDim.x + threadIdx.x;
    if (i >= out_size) return;
    int n = i / OUT_PER_NODE;
    out[i] = out[i] / fmaxf(d_cnt[n], 1.0f);
}

// ---------------- launch ----------------
extern "C" void kernel_launch(void* const* d_in, const int* in_sizes, int n_in,
                              void* d_out, int out_size) {
    const float* pos      = (const float*)d_in[0];
    const int*   A        = (const int*)d_in[1];
    const int*   batch    = (const int*)d_in[2];
    const int*   edge_src = (const int*)d_in[3];
    const int*   edge_dst = (const int*)d_in[4];
    const float* shifts   = (const float*)d_in[5];
    const float* cell     = (const float*)d_in[6];
    const float* emb      = (const float*)d_in[7];
    const float* fit_w1   = (const float*)d_in[8];
    const float* fit_b1   = (const float*)d_in[9];
    const float* fit_w2   = (const float*)d_in[10];
    const float* fit_b2   = (const float*)d_in[11];
    const float* fit_w3   = (const float*)d_in[12];
    const float* fit_b3   = (const float*)d_in[13];
    const float* fc_w1    = (const float*)d_in[14];
    const float* fc_w2    = (const float*)d_in[15];
    const float* fc_w3    = (const float*)d_in[16];
    const float* fc_w4    = (const float*)d_in[17];
    float* out = (float*)d_out;

    cudaFuncSetAttribute(k_main, cudaFuncAttributeMaxDynamicSharedMemorySize,
                         512 * 32 * (int)sizeof(float));

    int zn = out_size > N_NODES ? out_size : N_NODES;
    k_zero<<<(zn + 255) / 256, 256>>>(out, out_size);
    k_count<<<(N_EDGES + 255) / 256, 256>>>(edge_dst);
    k_node<<<(N_NODES + 255) / 256, 256>>>(emb, fit_w1, fit_b1, fit_w2, fit_b2,
                                           fit_w3, fit_b3, A);
    k_permute<<<(64 * 768 + 255) / 256, 256>>>(fc_w4);
    k_radial<<<(N_EDGES + 255) / 256, 256>>>(pos, batch, edge_src, edge_dst,
                                             shifts, cell, fc_w1, fc_w2, fc_w3);
    dim3 mg(98, 3);
    k_main<<<mg, 256, 512 * 32 * sizeof(float)>>>(pos, batch, edge_src, edge_dst,
                                                  shifts, cell, out);
    k_div<<<(out_size + 255) / 256, 256>>>(out, out_size);
}

// round 5
// speedup vs baseline: 2.0020x; 1.0326x over previous
#include <cuda_runtime.h>
#include <math.h>

#define N_NODES 20000
#define N_EDGES 160000
#define OUT_PER_NODE 36

typedef unsigned long long u64;

// ---------------- packed f32x2 helpers (sm_103a FFMA2 path) ----------------
__device__ __forceinline__ u64 pack2(float a, float b) {
    u64 r; asm("mov.b64 %0, {%1,%2};" : "=l"(r) : "f"(a), "f"(b)); return r;
}
__device__ __forceinline__ void unpack2(u64 v, float& a, float& b) {
    asm("mov.b64 {%0,%1}, %2;" : "=f"(a), "=f"(b) : "l"(v));
}
__device__ __forceinline__ void ffma2(u64& d, u64 a, u64 b) {
    asm("fma.rn.f32x2 %0, %1, %2, %0;" : "+l"(d) : "l"(a), "l"(b));
}

// ---------------- scratch ----------------
__device__ float d_Ai[N_NODES * 8];
__device__ float d_g3T[64 * N_EDGES];           // [c][e], coalesced in k_main
__device__ float d_M[3 * 512 * 32];             // [l][(c*8+u)][(v*4+w)]
__device__ float d_cnt[N_NODES];

// ---------------- kernel 1: zero output + cnt ----------------
__global__ void k_zero(float* out, int out_size) {
    int i = blockIdx.x * blockDim.x + threadIdx.x;
    if (i < out_size) out[i] = 0.0f;
    if (i < N_NODES) d_cnt[i] = 0.0f;
}

// ---------------- kernel 2: fused node MLP + fc_w4 permute ----------------
// blocks [0,79): node MLP;  blocks [79, 79+192): permute
#define NODE_BLOCKS 79
__global__ __launch_bounds__(256) void k_prep(
    const float* __restrict__ emb_table,
    const float* __restrict__ w1, const float* __restrict__ b1,
    const float* __restrict__ w2, const float* __restrict__ b2,
    const float* __restrict__ w3, const float* __restrict__ b3,
    const int* __restrict__ A,
    const float* __restrict__ fc_w4)
{
    int tid = threadIdx.x;
    if (blockIdx.x >= NODE_BLOCKS) {
        // ---- permute branch: fc_w4 [c][l][u][vw] -> d_M[l][(c*8+u)][vw] ----
        int idx = (blockIdx.x - NODE_BLOCKS) * 256 + tid;
        if (idx < 64 * 768) {
            int c = idx / 768;
            int rem = idx - c * 768;
            int l = rem / 256;
            int rem2 = rem - l * 256;
            int u = rem2 / 32;
            int vw = rem2 - u * 32;
            d_M[l * (512 * 32) + (c * 8 + u) * 32 + vw] = fc_w4[idx];
        }
        return;
    }

    __shared__ __align__(16) float s_w1[16 * 64];
    __shared__ __align__(16) float s_w2[64 * 32];
    __shared__ __align__(16) float s_w3[32 * 8];
    __shared__ float s_b1[64];
    __shared__ float s_b2[32];
    __shared__ float s_b3[8];
    for (int i = tid; i < 16 * 64; i += 256) s_w1[i] = w1[i];
    for (int i = tid; i < 64 * 32; i += 256) s_w2[i] = w2[i];
    for (int i = tid; i < 32 * 8;  i += 256) s_w3[i] = w3[i];
    if (tid < 64) s_b1[tid] = b1[tid];
    if (tid < 32) s_b2[tid] = b2[tid];
    if (tid < 8)  s_b3[tid] = b3[tid];
    __syncthreads();

    int n = blockIdx.x * 256 + tid;
    if (n >= N_NODES) return;

    int a = A[n];
    float e[16];
    #pragma unroll
    for (int i = 0; i < 16; i++) e[i] = emb_table[a * 16 + i];

    float h1[64];
    #pragma unroll
    for (int j = 0; j < 64; j++) h1[j] = s_b1[j];
    #pragma unroll
    for (int i = 0; i < 16; i++) {
        float ei = e[i];
        #pragma unroll
        for (int j = 0; j < 64; j++) h1[j] += ei * s_w1[i * 64 + j];
    }
    #pragma unroll
    for (int j = 0; j < 64; j++) { float x = h1[j]; h1[j] = x / (1.0f + __expf(-x)); }

    float h2[32];
    #pragma unroll
    for (int j = 0; j < 32; j++) h2[j] = s_b2[j];
    #pragma unroll
    for (int i = 0; i < 64; i++) {
        float hi = h1[i];
        #pragma unroll
        for (int j = 0; j < 32; j++) h2[j] += hi * s_w2[i * 32 + j];
    }
    #pragma unroll
    for (int j = 0; j < 32; j++) { float x = h2[j]; h2[j] = x / (1.0f + __expf(-x)); }

    float ai[8];
    #pragma unroll
    for (int j = 0; j < 8; j++) ai[j] = s_b3[j];
    #pragma unroll
    for (int i = 0; i < 32; i++) {
        float hi = h2[i];
        #pragma unroll
        for (int j = 0; j < 8; j++) ai[j] += hi * s_w3[i * 8 + j];
    }
    #pragma unroll
    for (int j = 0; j < 8; j++) d_Ai[n * 8 + j] = ai[j];
}

// ---------------- geometry helper ----------------
__device__ __forceinline__ void edge_geom(
    const float* __restrict__ pos, const int* __restrict__ batch,
    const float* __restrict__ shifts, const float* __restrict__ cell,
    int e, int s, int d, float& ex, float& ey, float& ez, float& r)
{
    float sx = shifts[e * 3 + 0], sy = shifts[e * 3 + 1], sz = shifts[e * 3 + 2];
    int b = batch[s];
    const float* C = cell + b * 9;
    float shx = sx * C[0] + sy * C[3] + sz * C[6];
    float shy = sx * C[1] + sy * C[4] + sz * C[7];
    float shz = sx * C[2] + sy * C[5] + sz * C[8];
    ex = pos[d * 3 + 0] - pos[s * 3 + 0] + shx;
    ey = pos[d * 3 + 1] - pos[s * 3 + 1] + shy;
    ez = pos[d * 3 + 2] - pos[s * 3 + 2] + shz;
    r = sqrtf(ex * ex + ey * ey + ez * ez);
}

// ---------------- kernel 3: edge radial chain -> g3T (packed FFMA2) ----------------
__global__ __launch_bounds__(256) void k_radial(
    const float* __restrict__ pos, const int* __restrict__ batch,
    const int* __restrict__ src, const int* __restrict__ dst,
    const float* __restrict__ shifts, const float* __restrict__ cell,
    const float* __restrict__ fw1, const float* __restrict__ fw2,
    const float* __restrict__ fw3)
{
    __shared__ __align__(16) float s_w1[16 * 64];
    __shared__ __align__(16) float s_w2[64 * 64];
    __shared__ __align__(16) float s_w3[64 * 64];
    int tid = threadIdx.x;
    for (int i = tid; i < 16 * 64; i += blockDim.x) s_w1[i] = fw1[i];
    for (int i = tid; i < 64 * 64; i += blockDim.x) s_w2[i] = fw2[i];
    for (int i = tid; i < 64 * 64; i += blockDim.x) s_w3[i] = fw3[i];
    __syncthreads();

    int e = blockIdx.x * blockDim.x + tid;
    if (e >= N_EDGES) return;

    int s = src[e], d = dst[e];
    float ex, ey, ez, r;
    edge_geom(pos, batch, shifts, cell, e, s, d, ex, ey, ez, r);

    const float step = 5.0f / 17.0f;
    const float inv_step = 17.0f / 5.0f;
    const float rb_scale = 4.0f / 1.12f;

    u64 acc[32];
    #pragma unroll
    for (int p = 0; p < 32; p++) acc[p] = 0ULL;
    #pragma unroll
    for (int i = 0; i < 16; i++) {
        float c = step * (float)(i + 1);
        float t = (r - c) * inv_step;
        float rb = __expf(-t * t) * rb_scale;
        u64 rr = pack2(rb, rb);
        const ulonglong2* row = (const ulonglong2*)&s_w1[i * 64];
        #pragma unroll
        for (int k = 0; k < 16; k++) {
            ulonglong2 m = row[k];
            ffma2(acc[2 * k + 0], rr, m.x);
            ffma2(acc[2 * k + 1], rr, m.y);
        }
    }
    float g[64];
    #pragma unroll
    for (int p = 0; p < 32; p++) {
        float a, b; unpack2(acc[p], a, b);
        a *= 0.25f; b *= 0.25f;
        g[2 * p + 0] = a / (1.0f + __expf(-a));
        g[2 * p + 1] = b / (1.0f + __expf(-b));
    }

    #pragma unroll
    for (int p = 0; p < 32; p++) acc[p] = 0ULL;
    #pragma unroll
    for (int i = 0; i < 64; i++) {
        u64 gi = pack2(g[i], g[i]);
        const ulonglong2* row = (const ulonglong2*)&s_w2[i * 64];
        #pragma unroll
        for (int k = 0; k < 16; k++) {
            ulonglong2 m = row[k];
            ffma2(acc[2 * k + 0], gi, m.x);
            ffma2(acc[2 * k + 1], gi, m.y);
        }
    }
    #pragma unroll
    for (int p = 0; p < 32; p++) {
        float a, b; unpack2(acc[p], a, b);
        a *= 0.125f; b *= 0.125f;
        g[2 * p + 0] = a / (1.0f + __expf(-a));
        g[2 * p + 1] = b / (1.0f + __expf(-b));
    }

    #pragma unroll
    for (int p = 0; p < 32; p++) acc[p] = 0ULL;
    #pragma unroll
    for (int i = 0; i < 64; i++) {
        u64 gi = pack2(g[i], g[i]);
        const ulonglong2* row = (const ulonglong2*)&s_w3[i * 64];
        #pragma unroll
        for (int k = 0; k < 16; k++) {
            ulonglong2 m = row[k];
            ffma2(acc[2 * k + 0], gi, m.x);
            ffma2(acc[2 * k + 1], gi, m.y);
        }
    }
    #pragma unroll
    for (int p = 0; p < 32; p++) {
        float a, b; unpack2(acc[p], a, b);
        a *= 0.125f; b *= 0.125f;
        d_g3T[(2 * p + 0) * N_EDGES + e] = a / (1.0f + __expf(-a));
        d_g3T[(2 * p + 1) * N_EDGES + e] = b / (1.0f + __expf(-b));
    }
}

// ---------------- epilogue helper (per edge) ----------------
__device__ __forceinline__ void do_epilogue(
    const u64 (&S2)[16], int e, int s, int l,
    const float* __restrict__ pos, const int* __restrict__ batch,
    const int* __restrict__ dst,
    const float* __restrict__ shifts, const float* __restrict__ cell,
    float* __restrict__ out)
{
    const float4* Ai4 = (const float4*)d_Ai;
    int dn = dst[e];
    float4 b0 = Ai4[dn * 2], b1 = Ai4[dn * 2 + 1];
    float Ad[8] = {b0.x, b0.y, b0.z, b0.w, b1.x, b1.y, b1.z, b1.w};

    u64 acc01 = 0ULL, acc23 = 0ULL;
    #pragma unroll
    for (int v = 0; v < 8; v++) {
        u64 av = pack2(Ad[v], Ad[v]);
        ffma2(acc01, av, S2[2 * v + 0]);
        ffma2(acc23, av, S2[2 * v + 1]);
    }
    float W[4];
    unpack2(acc01, W[0], W[1]);
    unpack2(acc23, W[2], W[3]);
    const float scale = 1.0f / 64.0f;
    #pragma unroll
    for (int w = 0; w < 4; w++) W[w] *= scale;

    float* od = out + dn * OUT_PER_NODE;
    if (l == 0) {
        #pragma unroll
        for (int w = 0; w < 4; w++) atomicAdd(&od[w], W[w]);
    } else {
        float ex, ey, ez, r;
        edge_geom(pos, batch, shifts, cell, e, s, dn, ex, ey, ez, r);
        float inv_r = 1.0f / fmaxf(r, 1e-9f);
        float x = ex * inv_r, y = ey * inv_r, z = ez * inv_r;
        if (l == 1) {
            const float s3 = 1.7320508075688772f;
            float sh1[3] = {s3 * y, s3 * z, s3 * x};
            #pragma unroll
            for (int w = 0; w < 4; w++)
                #pragma unroll
                for (int k = 0; k < 3; k++)
                    atomicAdd(&od[4 + w * 3 + k], W[w] * sh1[k]);
        } else {
            const float s15 = 3.872983346207417f;
            const float s5 = 2.23606797749979f;
            float sh2[5] = {s15 * x * y, s15 * y * z,
                            0.5f * s5 * (3.0f * z * z - 1.0f),
                            s15 * x * z, 0.5f * s15 * (x * x - y * y)};
            #pragma unroll
            for (int w = 0; w < 4; w++)
                #pragma unroll
                for (int k = 0; k < 5; k++)
                    atomicAdd(&od[16 + w * 5 + k], W[w] * sh2[k]);
        }
    }
}

// ---------------- kernel 4: main contraction, 2 edges/thread, MLP-4 g3 ----------------
__global__ __launch_bounds__(256, 2) void k_main(
    const float* __restrict__ pos, const int* __restrict__ batch,
    const int* __restrict__ src, const int* __restrict__ dst,
    const float* __restrict__ shifts, const float* __restrict__ cell,
    float* __restrict__ out)
{
    extern __shared__ float sM[];  // 512*32 floats = 64 KB (this block's l slice)
    const int l = blockIdx.y;
    const float* Ml = d_M + l * (512 * 32);
    for (int i = threadIdx.x; i < 512 * 32; i += 256) sM[i] = Ml[i];
    __syncthreads();

    const float4* Ai4 = (const float4*)d_Ai;

    for (int base = blockIdx.x * 512; base < N_EDGES; base += gridDim.x * 512) {
        int e0 = base + threadIdx.x;
        int e1 = e0 + 256;
        bool v0 = e0 < N_EDGES, v1 = e1 < N_EDGES;
        int ee0 = v0 ? e0 : 0;
        int ee1 = v1 ? e1 : 0;

        int s0 = src[ee0], s1 = src[ee1];
        float4 a0 = Ai4[s0 * 2], a1 = Ai4[s0 * 2 + 1];
        float As0[8] = {a0.x, a0.y, a0.z, a0.w, a1.x, a1.y, a1.z, a1.w};
        float4 c0 = Ai4[s1 * 2], c1 = Ai4[s1 * 2 + 1];
        float As1[8] = {c0.x, c0.y, c0.z, c0.w, c1.x, c1.y, c1.z, c1.w};

        u64 S0[16], S1[16];
        #pragma unroll
        for (int p = 0; p < 16; p++) { S0[p] = 0ULL; S1[p] = 0ULL; }

        #pragma unroll 1
        for (int c = 0; c < 64; c += 2) {
            // batched g3 loads: MLP = 4
            float g00 = __ldg(&d_g3T[c * N_EDGES + ee0]);
            float g01 = __ldg(&d_g3T[c * N_EDGES + ee1]);
            float g10 = __ldg(&d_g3T[(c + 1) * N_EDGES + ee0]);
            float g11 = __ldg(&d_g3T[(c + 1) * N_EDGES + ee1]);
            #pragma unroll
            for (int cc = 0; cc < 2; cc++) {
                float ga = cc ? g10 : g00;
                float gb = cc ? g11 : g01;
                const ulonglong2* row = (const ulonglong2*)&sM[(c + cc) * 256];
                #pragma unroll
                for (int u = 0; u < 8; u++) {
                    float f0 = ga * As0[u];
                    float f1 = gb * As1[u];
                    u64 ff0 = pack2(f0, f0);
                    u64 ff1 = pack2(f1, f1);
                    #pragma unroll
                    for (int k = 0; k < 8; k++) {
                        ulonglong2 m = row[u * 8 + k];
                        ffma2(S0[2 * k + 0], ff0, m.x);
                        ffma2(S0[2 * k + 1], ff0, m.y);
                        ffma2(S1[2 * k + 0], ff1, m.x);
                        ffma2(S1[2 * k + 1], ff1, m.y);
                    }
                }
            }
        }

        if (v0) do_epilogue(S0, e0, s0, l, pos, batch, dst, shifts, cell, out);
        if (v1) do_epilogue(S1, e1, s1, l, pos, batch, dst, shifts, cell, out);
    }
}

// ---------------- kernel 5: edge counts ----------------
__global__ void k_count(const int* __restrict__ edge_dst) {
    int e = blockIdx.x * blockDim.x + threadIdx.x;
    if (e < N_EDGES) atomicAdd(&d_cnt[edge_dst[e]], 1.0f);
}

// ---------------- kernel 6: divide by clipped count ----------------
__global__ void k_div(float* __restrict__ out, int out_size) {
    int i = blockIdx.x * blockDim.x + threadIdx.x;
    if (i >= out_size) return;
    int n = i / OUT_PER_NODE;
    out[i] = out[i] / fmaxf(d_cnt[n], 1.0f);
}

// ---------------- launch ----------------
extern "C" void kernel_launch(void* const* d_in, const int* in_sizes, int n_in,
                              void* d_out, int out_size) {
    const float* pos      = (const float*)d_in[0];
    const int*   A        = (const int*)d_in[1];
    const int*   batch    = (const int*)d_in[2];
    const int*   edge_src = (const int*)d_in[3];
    const int*   edge_dst = (const int*)d_in[4];
    const float* shifts   = (const float*)d_in[5];
    const float* cell     = (const float*)d_in[6];
    const float* emb      = (const float*)d_in[7];
    const float* fit_w1   = (const float*)d_in[8];
    const float* fit_b1   = (const float*)d_in[9];
    const float* fit_w2   = (const float*)d_in[10];
    const float* fit_b2   = (const float*)d_in[11];
    const float* fit_w3   = (const float*)d_in[12];
    const float* fit_b3   = (const float*)d_in[13];
    const float* fc_w1    = (const float*)d_in[14];
    const float* fc_w2    = (const float*)d_in[15];
    const float* fc_w3    = (const float*)d_in[16];
    const float* fc_w4    = (const float*)d_in[17];
    float* out = (float*)d_out;

    cudaFuncSetAttribute(k_main, cudaFuncAttributeMaxDynamicSharedMemorySize,
                         512 * 32 * (int)sizeof(float));

    int zn = out_size > N_NODES ? out_size : N_NODES;
    // launch order chosen so k_main is the 4th launch (ncu -s 5 -c 1 slot)
    k_zero<<<(zn + 255) / 256, 256>>>(out, out_size);
    k_prep<<<NODE_BLOCKS + 192, 256>>>(emb, fit_w1, fit_b1, fit_w2, fit_b2,
                                       fit_w3, fit_b3, A, fc_w4);
    k_radial<<<(N_EDGES + 255) / 256, 256>>>(pos, batch, edge_src, edge_dst,
                                             shifts, cell, fc_w1, fc_w2, fc_w3);
    dim3 mg(104, 3);
    k_main<<<mg, 256, 512 * 32 * sizeof(float)>>>(pos, batch, edge_src, edge_dst,
                                                  shifts, cell, out);
    k_count<<<(N_EDGES + 255) / 256, 256>>>(edge_dst);
    k_div<<<(out_size + 255) / 256, 256>>>(out, out_size);
}

// round 6
// speedup vs baseline: 3.7215x; 1.8589x over previous
#include <cuda_runtime.h>
#include <math.h>

#define N_NODES 20000
#define N_EDGES 160000
#define OUT_PER_NODE 36

typedef unsigned long long u64;

// ---------------- packed f32x2 helpers (sm_103a FFMA2 path) ----------------
__device__ __forceinline__ u64 pack2(float a, float b) {
    u64 r; asm("mov.b64 %0, {%1,%2};" : "=l"(r) : "f"(a), "f"(b)); return r;
}
__device__ __forceinline__ void unpack2(u64 v, float& a, float& b) {
    asm("mov.b64 {%0,%1}, %2;" : "=f"(a), "=f"(b) : "l"(v));
}
__device__ __forceinline__ void ffma2(u64& d, u64 a, u64 b) {
    asm("fma.rn.f32x2 %0, %1, %2, %0;" : "+l"(d) : "l"(a), "l"(b));
}
__device__ __forceinline__ float silu_f(float x) {
    return __fdividef(x, 1.0f + __expf(-x));
}

// ---------------- scratch ----------------
__device__ float d_Ai[N_NODES * 8];
__device__ float d_g3T[64 * N_EDGES];           // [c][e], coalesced in k_main
__device__ float d_M[3 * 512 * 32];             // [l][(c*8+u)][(v*4+w)]
__device__ float d_cnt[N_NODES];

// ---------------- kernel 1: zero output + cnt ----------------
__global__ void k_zero(float* out, int out_size) {
    int i = blockIdx.x * blockDim.x + threadIdx.x;
    if (i < out_size) out[i] = 0.0f;
    if (i < N_NODES) d_cnt[i] = 0.0f;
}

// ---------------- kernel 2: fused node MLP + fc_w4 permute ----------------
#define NODE_BLOCKS 79
__global__ __launch_bounds__(256) void k_prep(
    const float* __restrict__ emb_table,
    const float* __restrict__ w1, const float* __restrict__ b1,
    const float* __restrict__ w2, const float* __restrict__ b2,
    const float* __restrict__ w3, const float* __restrict__ b3,
    const int* __restrict__ A,
    const float* __restrict__ fc_w4)
{
    int tid = threadIdx.x;
    if (blockIdx.x >= NODE_BLOCKS) {
        int idx = (blockIdx.x - NODE_BLOCKS) * 256 + tid;
        if (idx < 64 * 768) {
            int c = idx / 768;
            int rem = idx - c * 768;
            int l = rem / 256;
            int rem2 = rem - l * 256;
            int u = rem2 / 32;
            int vw = rem2 - u * 32;
            d_M[l * (512 * 32) + (c * 8 + u) * 32 + vw] = fc_w4[idx];
        }
        return;
    }

    __shared__ __align__(16) float s_w1[16 * 64];
    __shared__ __align__(16) float s_w2[64 * 32];
    __shared__ __align__(16) float s_w3[32 * 8];
    __shared__ float s_b1[64];
    __shared__ float s_b2[32];
    __shared__ float s_b3[8];
    for (int i = tid; i < 16 * 64; i += 256) s_w1[i] = w1[i];
    for (int i = tid; i < 64 * 32; i += 256) s_w2[i] = w2[i];
    for (int i = tid; i < 32 * 8;  i += 256) s_w3[i] = w3[i];
    if (tid < 64) s_b1[tid] = b1[tid];
    if (tid < 32) s_b2[tid] = b2[tid];
    if (tid < 8)  s_b3[tid] = b3[tid];
    __syncthreads();

    int n = blockIdx.x * 256 + tid;
    if (n >= N_NODES) return;

    int a = A[n];
    float e[16];
    #pragma unroll
    for (int i = 0; i < 16; i++) e[i] = emb_table[a * 16 + i];

    float h1[64];
    #pragma unroll
    for (int j = 0; j < 64; j++) h1[j] = s_b1[j];
    #pragma unroll
    for (int i = 0; i < 16; i++) {
        float ei = e[i];
        #pragma unroll
        for (int j = 0; j < 64; j++) h1[j] += ei * s_w1[i * 64 + j];
    }
    #pragma unroll
    for (int j = 0; j < 64; j++) h1[j] = silu_f(h1[j]);

    float h2[32];
    #pragma unroll
    for (int j = 0; j < 32; j++) h2[j] = s_b2[j];
    #pragma unroll
    for (int i = 0; i < 64; i++) {
        float hi = h1[i];
        #pragma unroll
        for (int j = 0; j < 32; j++) h2[j] += hi * s_w2[i * 32 + j];
    }
    #pragma unroll
    for (int j = 0; j < 32; j++) h2[j] = silu_f(h2[j]);

    float ai[8];
    #pragma unroll
    for (int j = 0; j < 8; j++) ai[j] = s_b3[j];
    #pragma unroll
    for (int i = 0; i < 32; i++) {
        float hi = h2[i];
        #pragma unroll
        for (int j = 0; j < 8; j++) ai[j] += hi * s_w3[i * 8 + j];
    }
    #pragma unroll
    for (int j = 0; j < 8; j++) d_Ai[n * 8 + j] = ai[j];
}

// ---------------- geometry helper ----------------
__device__ __forceinline__ void edge_geom(
    const float* __restrict__ pos, const int* __restrict__ batch,
    const float* __restrict__ shifts, const float* __restrict__ cell,
    int e, int s, int d, float& ex, float& ey, float& ez, float& r)
{
    float sx = shifts[e * 3 + 0], sy = shifts[e * 3 + 1], sz = shifts[e * 3 + 2];
    int b = batch[s];
    const float* C = cell + b * 9;
    float shx = sx * C[0] + sy * C[3] + sz * C[6];
    float shy = sx * C[1] + sy * C[4] + sz * C[7];
    float shz = sx * C[2] + sy * C[5] + sz * C[8];
    ex = pos[d * 3 + 0] - pos[s * 3 + 0] + shx;
    ey = pos[d * 3 + 1] - pos[s * 3 + 1] + shy;
    ez = pos[d * 3 + 2] - pos[s * 3 + 2] + shz;
    r = sqrtf(ex * ex + ey * ey + ez * ez);
}

// ---------------- kernel 3: radial chain, reg-capped, pass-split ----------------
__global__ __launch_bounds__(128, 3) void k_radial(
    const float* __restrict__ pos, const int* __restrict__ batch,
    const int* __restrict__ src, const int* __restrict__ dst,
    const float* __restrict__ shifts, const float* __restrict__ cell,
    const float* __restrict__ fw1, const float* __restrict__ fw2,
    const float* __restrict__ fw3)
{
    __shared__ __align__(16) float s_w1[16 * 64];
    __shared__ __align__(16) float s_w2[64 * 64];
    __shared__ __align__(16) float s_w3[64 * 64];
    int tid = threadIdx.x;
    for (int i = tid; i < 16 * 64; i += 128) s_w1[i] = fw1[i];
    for (int i = tid; i < 64 * 64; i += 128) s_w2[i] = fw2[i];
    for (int i = tid; i < 64 * 64; i += 128) s_w3[i] = fw3[i];
    __syncthreads();

    int e = blockIdx.x * 128 + tid;
    if (e >= N_EDGES) return;

    int s = src[e], d = dst[e];
    float ex, ey, ez, r;
    edge_geom(pos, batch, shifts, cell, e, s, d, ex, ey, ez, r);

    const float step = 5.0f / 17.0f;
    const float inv_step = 17.0f / 5.0f;
    const float rb_scale = 4.0f / 1.12f;

    float rb[16];
    #pragma unroll
    for (int i = 0; i < 16; i++) {
        float c = step * (float)(i + 1);
        float t = (r - c) * inv_step;
        rb[i] = __expf(-t * t) * rb_scale;
    }

    // ---- layer 1: [16]->[64], two half-passes of 32 outputs ----
    float g1[64];
    #pragma unroll
    for (int h = 0; h < 2; h++) {
        u64 acc[16];
        #pragma unroll
        for (int p = 0; p < 16; p++) acc[p] = 0ULL;
        #pragma unroll 4
        for (int i = 0; i < 16; i++) {
            u64 rr = pack2(rb[i], rb[i]);
            const ulonglong2* row = (const ulonglong2*)&s_w1[i * 64 + h * 32];
            #pragma unroll
            for (int k = 0; k < 8; k++) {
                ulonglong2 m = row[k];
                ffma2(acc[2 * k + 0], rr, m.x);
                ffma2(acc[2 * k + 1], rr, m.y);
            }
        }
        #pragma unroll
        for (int p = 0; p < 16; p++) {
            float a, b; unpack2(acc[p], a, b);
            g1[h * 32 + 2 * p + 0] = silu_f(a * 0.25f);
            g1[h * 32 + 2 * p + 1] = silu_f(b * 0.25f);
        }
    }

    // ---- layer 2: [64]->[64], four quarter-passes of 16 outputs ----
    float g2[64];
    #pragma unroll
    for (int q = 0; q < 4; q++) {
        u64 acc[8];
        #pragma unroll
        for (int p = 0; p < 8; p++) acc[p] = 0ULL;
        #pragma unroll 4
        for (int i = 0; i < 64; i++) {
            u64 gi = pack2(g1[i], g1[i]);
            const ulonglong2* row = (const ulonglong2*)&s_w2[i * 64 + q * 16];
            #pragma unroll
            for (int k = 0; k < 4; k++) {
                ulonglong2 m = row[k];
                ffma2(acc[2 * k + 0], gi, m.x);
                ffma2(acc[2 * k + 1], gi, m.y);
            }
        }
        #pragma unroll
        for (int p = 0; p < 8; p++) {
            float a, b; unpack2(acc[p], a, b);
            g2[q * 16 + 2 * p + 0] = silu_f(a * 0.125f);
            g2[q * 16 + 2 * p + 1] = silu_f(b * 0.125f);
        }
    }

    // ---- layer 3: [64]->[64], four quarter-passes, write to gmem ----
    #pragma unroll
    for (int q = 0; q < 4; q++) {
        u64 acc[8];
        #pragma unroll
        for (int p = 0; p < 8; p++) acc[p] = 0ULL;
        #pragma unroll 4
        for (int i = 0; i < 64; i++) {
            u64 gi = pack2(g2[i], g2[i]);
            const ulonglong2* row = (const ulonglong2*)&s_w3[i * 64 + q * 16];
            #pragma unroll
            for (int k = 0; k < 4; k++) {
                ulonglong2 m = row[k];
                ffma2(acc[2 * k + 0], gi, m.x);
                ffma2(acc[2 * k + 1], gi, m.y);
            }
        }
        #pragma unroll
        for (int p = 0; p < 8; p++) {
            float a, b; unpack2(acc[p], a, b);
            d_g3T[(q * 16 + 2 * p + 0) * N_EDGES + e] = silu_f(a * 0.125f);
            d_g3T[(q * 16 + 2 * p + 1) * N_EDGES + e] = silu_f(b * 0.125f);
        }
    }
}

// ---------------- epilogue helper (per edge, vw-half slice) ----------------
__device__ __forceinline__ void do_epilogue(
    const u64 (&S2)[8], int e, int s, int l, int h,
    const float* __restrict__ pos, const int* __restrict__ batch,
    const int* __restrict__ dst,
    const float* __restrict__ shifts, const float* __restrict__ cell,
    float* __restrict__ out)
{
    const float4* Ai4 = (const float4*)d_Ai;
    int dn = dst[e];
    float4 b0 = Ai4[dn * 2], b1 = Ai4[dn * 2 + 1];
    float Adh[4];
    if (h == 0) { Adh[0] = b0.x; Adh[1] = b0.y; Adh[2] = b0.z; Adh[3] = b0.w; }
    else        { Adh[0] = b1.x; Adh[1] = b1.y; Adh[2] = b1.z; Adh[3] = b1.w; }

    u64 acc01 = 0ULL, acc23 = 0ULL;
    #pragma unroll
    for (int v = 0; v < 4; v++) {
        u64 av = pack2(Adh[v], Adh[v]);
        ffma2(acc01, av, S2[2 * v + 0]);
        ffma2(acc23, av, S2[2 * v + 1]);
    }
    float W[4];
    unpack2(acc01, W[0], W[1]);
    unpack2(acc23, W[2], W[3]);
    const float scale = 1.0f / 64.0f;
    #pragma unroll
    for (int w = 0; w < 4; w++) W[w] *= scale;

    float* od = out + dn * OUT_PER_NODE;
    if (l == 0) {
        #pragma unroll
        for (int w = 0; w < 4; w++) atomicAdd(&od[w], W[w]);
    } else {
        float ex, ey, ez, r;
        edge_geom(pos, batch, shifts, cell, e, s, dn, ex, ey, ez, r);
        float inv_r = __fdividef(1.0f, fmaxf(r, 1e-9f));
        float x = ex * inv_r, y = ey * inv_r, z = ez * inv_r;
        if (l == 1) {
            const float s3 = 1.7320508075688772f;
            float sh1[3] = {s3 * y, s3 * z, s3 * x};
            #pragma unroll
            for (int w = 0; w < 4; w++)
                #pragma unroll
                for (int k = 0; k < 3; k++)
                    atomicAdd(&od[4 + w * 3 + k], W[w] * sh1[k]);
        } else {
            const float s15 = 3.872983346207417f;
            const float s5 = 2.23606797749979f;
            float sh2[5] = {s15 * x * y, s15 * y * z,
                            0.5f * s5 * (3.0f * z * z - 1.0f),
                            s15 * x * z, 0.5f * s15 * (x * x - y * y)};
            #pragma unroll
            for (int w = 0; w < 4; w++)
                #pragma unroll
                for (int k = 0; k < 5; k++)
                    atomicAdd(&od[16 + w * 5 + k], W[w] * sh2[k]);
        }
    }
}

// ---------------- kernel 4: main contraction, 6 (l,half) slices, 3 CTA/SM ----------------
__global__ __launch_bounds__(256, 3) void k_main(
    const float* __restrict__ pos, const int* __restrict__ batch,
    const int* __restrict__ src, const int* __restrict__ dst,
    const float* __restrict__ shifts, const float* __restrict__ cell,
    float* __restrict__ out)
{
    extern __shared__ float sM[];  // 512*16 floats = 32 KB (l, vw-half slice)
    const int l = blockIdx.y >> 1;
    const int h = blockIdx.y & 1;
    const float* Ml = d_M + l * (512 * 32) + h * 16;
    for (int i = threadIdx.x; i < 512 * 16; i += 256) {
        int cu = i >> 4, j = i & 15;
        sM[i] = Ml[cu * 32 + j];
    }
    __syncthreads();

    const float4* Ai4 = (const float4*)d_Ai;

    for (int base = blockIdx.x * 512; base < N_EDGES; base += gridDim.x * 512) {
        int e0 = base + threadIdx.x;
        int e1 = e0 + 256;
        bool v0 = e0 < N_EDGES, v1 = e1 < N_EDGES;
        int ee0 = v0 ? e0 : 0;
        int ee1 = v1 ? e1 : 0;

        int s0 = src[ee0], s1 = src[ee1];
        float4 a0 = Ai4[s0 * 2], a1 = Ai4[s0 * 2 + 1];
        float As0[8] = {a0.x, a0.y, a0.z, a0.w, a1.x, a1.y, a1.z, a1.w};
        float4 c0 = Ai4[s1 * 2], c1 = Ai4[s1 * 2 + 1];
        float As1[8] = {c0.x, c0.y, c0.z, c0.w, c1.x, c1.y, c1.z, c1.w};

        u64 S0[8], S1[8];
        #pragma unroll
        for (int p = 0; p < 8; p++) { S0[p] = 0ULL; S1[p] = 0ULL; }

        #pragma unroll 1
        for (int c = 0; c < 64; c += 2) {
            float g00 = __ldg(&d_g3T[c * N_EDGES + ee0]);
            float g01 = __ldg(&d_g3T[c * N_EDGES + ee1]);
            float g10 = __ldg(&d_g3T[(c + 1) * N_EDGES + ee0]);
            float g11 = __ldg(&d_g3T[(c + 1) * N_EDGES + ee1]);
            #pragma unroll
            for (int cc = 0; cc < 2; cc++) {
                float ga = cc ? g10 : g00;
                float gb = cc ? g11 : g01;
                const ulonglong2* row = (const ulonglong2*)&sM[(c + cc) * 128];
                #pragma unroll
                for (int u = 0; u < 8; u++) {
                    float f0 = ga * As0[u];
                    float f1 = gb * As1[u];
                    u64 ff0 = pack2(f0, f0);
                    u64 ff1 = pack2(f1, f1);
                    #pragma unroll
                    for (int k = 0; k < 4; k++) {
                        ulonglong2 m = row[u * 4 + k];
                        ffma2(S0[2 * k + 0], ff0, m.x);
                        ffma2(S0[2 * k + 1], ff0, m.y);
                        ffma2(S1[2 * k + 0], ff1, m.x);
                        ffma2(S1[2 * k + 1], ff1, m.y);
                    }
                }
            }
        }

        if (v0) do_epilogue(S0, e0, s0, l, h, pos, batch, dst, shifts, cell, out);
        if (v1) do_epilogue(S1, e1, s1, l, h, pos, batch, dst, shifts, cell, out);
    }
}

// ---------------- kernel 5/6: counts + divide ----------------
__global__ void k_count(const int* __restrict__ edge_dst) {
    int e = blockIdx.x * blockDim.x + threadIdx.x;
    if (e < N_EDGES) atomicAdd(&d_cnt[edge_dst[e]], 1.0f);
}
__global__ void k_div(float* __restrict__ out, int out_size) {
    int i = blockIdx.x * blockDim.x + threadIdx.x;
    if (i >= out_size) return;
    int n = i / OUT_PER_NODE;
    out[i] = out[i] / fmaxf(d_cnt[n], 1.0f);
}

// ---------------- launch ----------------
extern "C" void kernel_launch(void* const* d_in, const int* in_sizes, int n_in,
                              void* d_out, int out_size) {
    const float* pos      = (const float*)d_in[0];
    const int*   A        = (const int*)d_in[1];
    const int*   batch    = (const int*)d_in[2];
    const int*   edge_src = (const int*)d_in[3];
    const int*   edge_dst = (const int*)d_in[4];
    const float* shifts   = (const float*)d_in[5];
    const float* cell     = (const float*)d_in[6];
    const float* emb      = (const float*)d_in[7];
    const float* fit_w1   = (const float*)d_in[8];
    const float* fit_b1   = (const float*)d_in[9];
    const float* fit_w2   = (const float*)d_in[10];
    const float* fit_b2   = (const float*)d_in[11];
    const float* fit_w3   = (const float*)d_in[12];
    const float* fit_b3   = (const float*)d_in[13];
    const float* fc_w1    = (const float*)d_in[14];
    const float* fc_w2    = (const float*)d_in[15];
    const float* fc_w3    = (const float*)d_in[16];
    const float* fc_w4    = (const float*)d_in[17];
    float* out = (float*)d_out;

    cudaFuncSetAttribute(k_main, cudaFuncAttributeMaxDynamicSharedMemorySize,
                         512 * 16 * (int)sizeof(float));

    int zn = out_size > N_NODES ? out_size : N_NODES;
    // k_main kept as 4th launch (ncu capture slot)
    k_zero<<<(zn + 255) / 256, 256>>>(out, out_size);
    k_prep<<<NODE_BLOCKS + 192, 256>>>(emb, fit_w1, fit_b1, fit_w2, fit_b2,
                                       fit_w3, fit_b3, A, fc_w4);
    k_radial<<<(N_EDGES + 127) / 128, 128>>>(pos, batch, edge_src, edge_dst,
                                             shifts, cell, fc_w1, fc_w2, fc_w3);
    dim3 mg(313, 6);
    k_main<<<mg, 256, 512 * 16 * sizeof(float)>>>(pos, batch, edge_src, edge_dst,
                                                  shifts, cell, out);
    k_count<<<(N_EDGES + 255) / 256, 256>>>(edge_dst);
    k_div<<<(out_size + 255) / 256, 256>>>(out, out_size);
}